// round 3
// baseline (speedup 1.0000x reference)
#include <cuda_runtime.h>
#include <cstdint>

// ---------------------------------------------------------------------------
// 2-layer GRU (256 units), B=4096, 64 warmup + 127 closed-loop decode steps.
// Persistent kernel: 128 CTAs x 32 rows, tf32 mma.sync tensor cores.
// Weights pre-permuted into fragment order (prep kernel) -> LDG.128 streams.
// ---------------------------------------------------------------------------

#define UNITS   256
#define G3      768
#define NROWS   32
#define NCTA    128
#define TSTEPS  191
#define WARM    64
#define HFS     260

#define L1_SLABS 33
#define L2_SLABS 64
#define L1_F4   (L1_SLABS*1536)   // 50688 float4
#define L2_F4   (L2_SLABS*1536)   // 98304 float4
#define TOT_F4  (L1_F4 + L2_F4)

__device__ float4 g_wts[TOT_F4];   // L1 blob | L2 blob, fragment-ordered tf32

// ---- smem layout (float offsets) ----
#define OFF_HA1 0
#define SZ_HA1  (2*L1_SLABS*32*4)            // 8448
#define OFF_HA2 (OFF_HA1 + SZ_HA1)
#define SZ_HA2  (2*32*32*4)                  // 8192
#define OFF_HF1 (OFF_HA2 + SZ_HA2)
#define OFF_HF2 (OFF_HF1 + NROWS*HFS)
#define OFF_B1  (OFF_HF2 + NROWS*HFS)
#define OFF_B2  (OFF_B1 + 2*G3)
#define OFF_WD  (OFF_B2 + 2*G3)
#define OFF_BD  (OFF_WD + UNITS*5)
#define OFF_PRS (OFF_BD + 8)
#define OFF_PART (OFF_PRS + NROWS*5)
#define SMEM_FLOATS (OFF_PART + 8*160)
#define SMEM_BYTES  (SMEM_FLOATS*4)

// ---------------------------------------------------------------------------
__device__ __forceinline__ float f2tf(float f){
    uint32_t r; asm("cvt.rna.tf32.f32 %0, %1;" : "=r"(r) : "f"(f));
    return __uint_as_float(r);
}

__device__ __forceinline__ void mma_t(float (&c)[4], const uint4& a, uint32_t b0, uint32_t b1){
    asm volatile(
        "mma.sync.aligned.m16n8k8.row.col.f32.tf32.tf32.f32 "
        "{%0,%1,%2,%3},{%4,%5,%6,%7},{%8,%9},{%0,%1,%2,%3};\n"
        : "+f"(c[0]), "+f"(c[1]), "+f"(c[2]), "+f"(c[3])
        : "r"(a.x), "r"(a.y), "r"(a.z), "r"(a.w), "r"(b0), "r"(b1));
}

__device__ __forceinline__ float sigf(float x){
    float e = __expf(-x);
    return __fdividef(1.f, 1.f + e);
}
__device__ __forceinline__ float tanhf_(float x){
    float e = __expf(2.f * x);
    return 1.f - __fdividef(2.f, e + 1.f);
}

// One k8-slab of one gate: 2 LDG.128 (B frags for tt0..3), 8 mma.
#define GATE_SLAB(ACC, Bq, a0, a1) do {                    \
    uint4 b0_ = __ldg((Bq));                               \
    uint4 b1_ = __ldg((Bq) + 256);                         \
    mma_t(ACC[0][0], a0, b0_.x, b0_.y);                    \
    mma_t(ACC[1][0], a1, b0_.x, b0_.y);                    \
    mma_t(ACC[0][1], a0, b0_.z, b0_.w);                    \
    mma_t(ACC[1][1], a1, b0_.z, b0_.w);                    \
    mma_t(ACC[0][2], a0, b1_.x, b1_.y);                    \
    mma_t(ACC[1][2], a1, b1_.x, b1_.y);                    \
    mma_t(ACC[0][3], a0, b1_.z, b1_.w);                    \
    mma_t(ACC[1][3], a1, b1_.z, b1_.w);                    \
} while (0)

// ---------------------------------------------------------------------------
// prep: permute U1|W1pad -> L1 blob, W2|U2 -> L2 blob, tf32-rounded.
// float4 element (slab,g,t2,w,lane): j in 0..3: tt=2*t2+(j>>1), q=j&1,
//   k = slab*8 + (lane&3) + 4q, col = g*256 + w*32 + tt*8 + (lane>>2).
__global__ void prep_kernel(const float* __restrict__ W1, const float* __restrict__ U1,
                            const float* __restrict__ W2, const float* __restrict__ U2){
    for (int idx = blockIdx.x*blockDim.x + threadIdx.x; idx < TOT_F4;
         idx += gridDim.x*blockDim.x){
        int li   = (idx < L1_F4) ? idx : idx - L1_F4;
        int lane = li & 31;
        int w    = (li >> 5) & 7;
        int t2   = (li >> 8) & 1;
        int g    = (li >> 9) % 3;
        int slab = (li >> 9) / 3;
        int lc = lane & 3, lr = lane >> 2;
        float v[4];
        #pragma unroll
        for (int j = 0; j < 4; j++){
            int q  = j & 1;
            int tt = t2*2 + (j >> 1);
            int col = g*256 + w*32 + tt*8 + lr;
            int kk  = lc + 4*q;
            float s;
            if (idx < L1_F4){
                if (slab < 32) s = U1[(slab*8 + kk)*G3 + col];
                else           s = (kk < 6) ? W1[kk*G3 + col] : 0.f;
            } else {
                if (slab < 32) s = W2[(slab*8 + kk)*G3 + col];
                else           s = U2[((slab-32)*8 + kk)*G3 + col];
            }
            uint32_t r; asm("cvt.rna.tf32.f32 %0, %1;" : "=r"(r) : "f"(s));
            v[j] = __uint_as_float(r);
        }
        g_wts[idx] = make_float4(v[0], v[1], v[2], v[3]);
    }
}

// ---------------------------------------------------------------------------
__global__ void __launch_bounds__(256, 1)
gru_kernel(const float* __restrict__ inputs, const float* __restrict__ gb1,
           const float* __restrict__ gb2, const float* __restrict__ gWd,
           const float* __restrict__ gbd, float* __restrict__ out){
    extern __shared__ __align__(16) float sm[];
    float* hF1 = sm + OFF_HF1;
    float* hF2 = sm + OFF_HF2;
    float* b1s = sm + OFF_B1;
    float* b2s = sm + OFF_B2;
    float* wds = sm + OFF_WD;
    float* bds = sm + OFF_BD;
    float* prs = sm + OFF_PRS;
    float* part= sm + OFF_PART;

    const int tid  = threadIdx.x;
    const int lane = tid & 31;
    const int warp = tid >> 5;
    const int lr   = lane >> 2;
    const int lc   = lane & 3;
    const int u0   = warp * 32;
    const int wl   = warp*32 + lane;
    const int row0 = blockIdx.x * NROWS;

    // init persistent smem
    for (int i = tid; i < 2*G3;    i += 256) b1s[i] = gb1[i];
    for (int i = tid; i < 2*G3;    i += 256) b2s[i] = gb2[i];
    for (int i = tid; i < UNITS*5; i += 256) wds[i] = gWd[i];
    if (tid < 5) bds[tid] = gbd[tid];
    for (int i = tid; i < SZ_HA1;    i += 256) sm[OFF_HA1 + i] = 0.f;
    for (int i = tid; i < SZ_HA2;    i += 256) sm[OFF_HA2 + i] = 0.f;
    for (int i = tid; i < NROWS*HFS; i += 256){ hF1[i] = 0.f; hF2[i] = 0.f; }
    if (tid < NROWS*5) prs[tid] = 0.f;
    __syncthreads();

    const uint4* hA1u = (const uint4*)(sm + OFF_HA1);
    const uint4* hA2u = (const uint4*)(sm + OFF_HA2);
    const uint4* B1b  = ((const uint4*)g_wts) + wl;
    const uint4* B2b  = ((const uint4*)g_wts) + L1_F4 + wl;

    float az[2][4][4], ar[2][4][4], axh[2][4][4], arh[2][4][4];
    float hn[2][4][4];

    for (int t = 0; t < TSTEPS; t++){
        // ---- assemble x into hA1 slab 32 ----
        if (tid < NROWS){
            int row = tid, grow = row0 + row;
            const float* ip = inputs + ((size_t)grow*192 + t)*6;
            float xv[8];
            if (t < WARM){
                #pragma unroll
                for (int i = 0; i < 6; i++) xv[i] = ip[i];
            } else {
                xv[0] = ip[0];
                #pragma unroll
                for (int i = 1; i < 6; i++) xv[i] = prs[row*5 + i - 1];
            }
            xv[6] = 0.f; xv[7] = 0.f;
            int m = row >> 4, r = row & 15, rl = r & 7, hi = r >> 3;
            #pragma unroll
            for (int i = 0; i < 8; i++){
                int lcc = i & 3, q = i >> 2;
                int ln = rl*4 + lcc, j = hi + 2*q;
                sm[OFF_HA1 + ((m*L1_SLABS + 32)*32 + ln)*4 + j] = f2tf(xv[i]);
            }
        }
        __syncthreads();                                   // S1

        // ---- layer 1 GEMMs ----
        #pragma unroll
        for (int m = 0; m < 2; m++)
            #pragma unroll
            for (int tt = 0; tt < 4; tt++)
                #pragma unroll
                for (int c = 0; c < 4; c++){
                    az[m][tt][c]=0.f; ar[m][tt][c]=0.f;
                    axh[m][tt][c]=0.f; arh[m][tt][c]=0.f;
                }
        for (int s = 0; s < 32; s++){
            uint4 a0 = hA1u[(0*L1_SLABS + s)*32 + lane];
            uint4 a1 = hA1u[(1*L1_SLABS + s)*32 + lane];
            const uint4* Bs = B1b + s*1536;
            GATE_SLAB(az,  Bs,        a0, a1);
            GATE_SLAB(ar,  Bs + 512,  a0, a1);
            GATE_SLAB(arh, Bs + 1024, a0, a1);
        }
        {   // x slab (32): z,r merged; h-gate -> xh
            uint4 a0 = hA1u[(0*L1_SLABS + 32)*32 + lane];
            uint4 a1 = hA1u[(1*L1_SLABS + 32)*32 + lane];
            const uint4* Bs = B1b + 32*1536;
            GATE_SLAB(az,  Bs,        a0, a1);
            GATE_SLAB(ar,  Bs + 512,  a0, a1);
            GATE_SLAB(axh, Bs + 1024, a0, a1);
        }

        // ---- layer 1 gate math (state in hF1, full fp32) ----
        #pragma unroll
        for (int tt = 0; tt < 4; tt++)
            #pragma unroll
            for (int cc = 0; cc < 2; cc++){
                int uc = u0 + tt*8 + 2*lc + cc;
                float bz  = b1s[uc]       + b1s[G3 + uc];
                float br  = b1s[256 + uc] + b1s[G3 + 256 + uc];
                float bxh = b1s[512 + uc];
                float brh = b1s[G3 + 512 + uc];
                #pragma unroll
                for (int m = 0; m < 2; m++)
                    #pragma unroll
                    for (int hi = 0; hi < 2; hi++){
                        int c = hi*2 + cc;
                        int row = 16*m + lr + 8*hi;
                        float z = sigf(az[m][tt][c] + bz);
                        float r = sigf(ar[m][tt][c] + br);
                        float hh = tanhf_(axh[m][tt][c] + bxh + r*(arh[m][tt][c] + brh));
                        float ho = hF1[row*HFS + uc];
                        float v  = z*ho + (1.f - z)*hh;
                        hF1[row*HFS + uc] = v;
                        hn[m][tt][c] = v;
                    }
            }
        __syncthreads();                                   // S2 (hA1 reads done)
        #pragma unroll
        for (int tt = 0; tt < 4; tt++)
            #pragma unroll
            for (int cc = 0; cc < 2; cc++){
                int kc = 2*lc + cc, lcc = kc & 3, q = kc >> 2;
                #pragma unroll
                for (int m = 0; m < 2; m++)
                    #pragma unroll
                    for (int hi = 0; hi < 2; hi++)
                        sm[OFF_HA1 + ((m*L1_SLABS + warp*4 + tt)*32 + lr*4 + lcc)*4
                           + hi + 2*q] = f2tf(hn[m][tt][hi*2 + cc]);
            }
        __syncthreads();                                   // S3

        // ---- layer 2 GEMMs: slabs 0-31 A=h1new(W2, h->xh), 32-63 A=h2(U2, h->rh)
        #pragma unroll
        for (int m = 0; m < 2; m++)
            #pragma unroll
            for (int tt = 0; tt < 4; tt++)
                #pragma unroll
                for (int c = 0; c < 4; c++){
                    az[m][tt][c]=0.f; ar[m][tt][c]=0.f;
                    axh[m][tt][c]=0.f; arh[m][tt][c]=0.f;
                }
        for (int s = 0; s < 32; s++){
            uint4 a0 = hA1u[(0*L1_SLABS + s)*32 + lane];
            uint4 a1 = hA1u[(1*L1_SLABS + s)*32 + lane];
            const uint4* Bs = B2b + s*1536;
            GATE_SLAB(az,  Bs,        a0, a1);
            GATE_SLAB(ar,  Bs + 512,  a0, a1);
            GATE_SLAB(axh, Bs + 1024, a0, a1);
        }
        for (int s = 32; s < 64; s++){
            uint4 a0 = hA2u[(0*32 + (s-32))*32 + lane];
            uint4 a1 = hA2u[(1*32 + (s-32))*32 + lane];
            const uint4* Bs = B2b + s*1536;
            GATE_SLAB(az,  Bs,        a0, a1);
            GATE_SLAB(ar,  Bs + 512,  a0, a1);
            GATE_SLAB(arh, Bs + 1024, a0, a1);
        }

        // ---- layer 2 gate math + pred partials ----
        float ps[4][5];
        #pragma unroll
        for (int ri = 0; ri < 4; ri++)
            #pragma unroll
            for (int o = 0; o < 5; o++) ps[ri][o] = 0.f;

        #pragma unroll
        for (int tt = 0; tt < 4; tt++)
            #pragma unroll
            for (int cc = 0; cc < 2; cc++){
                int uc = u0 + tt*8 + 2*lc + cc;
                float bz  = b2s[uc]       + b2s[G3 + uc];
                float br  = b2s[256 + uc] + b2s[G3 + 256 + uc];
                float bxh = b2s[512 + uc];
                float brh = b2s[G3 + 512 + uc];
                float wdv[5];
                #pragma unroll
                for (int o = 0; o < 5; o++) wdv[o] = wds[uc*5 + o];
                #pragma unroll
                for (int m = 0; m < 2; m++)
                    #pragma unroll
                    for (int hi = 0; hi < 2; hi++){
                        int c = hi*2 + cc;
                        int row = 16*m + lr + 8*hi;
                        float z = sigf(az[m][tt][c] + bz);
                        float r = sigf(ar[m][tt][c] + br);
                        float hh = tanhf_(axh[m][tt][c] + bxh + r*(arh[m][tt][c] + brh));
                        float ho = hF2[row*HFS + uc];
                        float v  = z*ho + (1.f - z)*hh;
                        hF2[row*HFS + uc] = v;
                        hn[m][tt][c] = v;
                        int ri = 2*m + hi;   // row = lr + 8*ri
                        #pragma unroll
                        for (int o = 0; o < 5; o++) ps[ri][o] += v * wdv[o];
                    }
            }
        // reduce pred partials over the 4 lc lanes
        #pragma unroll
        for (int ri = 0; ri < 4; ri++)
            #pragma unroll
            for (int o = 0; o < 5; o++){
                ps[ri][o] += __shfl_xor_sync(0xffffffffu, ps[ri][o], 1);
                ps[ri][o] += __shfl_xor_sync(0xffffffffu, ps[ri][o], 2);
            }
        if (lc == 0){
            #pragma unroll
            for (int ri = 0; ri < 4; ri++)
                #pragma unroll
                for (int o = 0; o < 5; o++)
                    part[warp*160 + (lr + 8*ri)*5 + o] = ps[ri][o];
        }
        __syncthreads();                                   // S4 (hA2 reads + part done)

        // write h2new to hA2
        #pragma unroll
        for (int tt = 0; tt < 4; tt++)
            #pragma unroll
            for (int cc = 0; cc < 2; cc++){
                int kc = 2*lc + cc, lcc = kc & 3, q = kc >> 2;
                #pragma unroll
                for (int m = 0; m < 2; m++)
                    #pragma unroll
                    for (int hi = 0; hi < 2; hi++)
                        sm[OFF_HA2 + ((m*32 + warp*4 + tt)*32 + lr*4 + lcc)*4
                           + hi + 2*q] = f2tf(hn[m][tt][hi*2 + cc]);
            }

        // final pred reduce + output
        if (tid < 160){
            int row = tid / 5, o = tid % 5;
            float s = bds[o];
            #pragma unroll
            for (int w = 0; w < 8; w++) s += part[w*160 + tid];
            prs[tid] = s;
            int grow = row0 + row;
            int tout = (t < WARM) ? t : t + 1;
            out[(size_t)grow*960 + tout*5 + o] = s;
            if (t == WARM - 1) out[(size_t)grow*960 + WARM*5 + o] = s;
        }
        __syncthreads();                                   // S5
    }
}

// ---------------------------------------------------------------------------
extern "C" void kernel_launch(void* const* d_in, const int* in_sizes, int n_in,
                              void* d_out, int out_size) {
    (void)in_sizes; (void)n_in; (void)out_size;
    const float* inputs = (const float*)d_in[0];
    const float* W1 = (const float*)d_in[1];
    const float* U1 = (const float*)d_in[2];
    const float* b1 = (const float*)d_in[3];
    const float* W2 = (const float*)d_in[4];
    const float* U2 = (const float*)d_in[5];
    const float* b2 = (const float*)d_in[6];
    const float* Wd = (const float*)d_in[7];
    const float* bd = (const float*)d_in[8];
    float* out = (float*)d_out;

    cudaFuncSetAttribute(gru_kernel, cudaFuncAttributeMaxDynamicSharedMemorySize,
                         SMEM_BYTES);
    prep_kernel<<<(TOT_F4 + 255)/256, 256>>>(W1, U1, W2, U2);
    gru_kernel<<<NCTA, 256, SMEM_BYTES>>>(inputs, b1, b2, Wd, bd, out);
}

// round 4
// speedup vs baseline: 1.0988x; 1.0988x over previous
#include <cuda_runtime.h>
#include <cstdint>

// ---------------------------------------------------------------------------
// 2-layer GRU (256 units), B=4096, 64 warmup + 127 closed-loop decode steps.
// Persistent kernel: 128 CTAs x 32 rows x 512 threads (16 warps x 16 units),
// tf32 mma.sync tensor cores, weights pre-permuted to fragment order.
// ---------------------------------------------------------------------------

#define UNITS   256
#define G3      768
#define NROWS   32
#define NCTA    128
#define NTHREADS 512
#define TSTEPS  191
#define WARM    64
#define HFS     260

#define L1_SLABS 33
#define L2_SLABS 64
#define L1_F4   (L1_SLABS*1536)   // 50688 float4
#define L2_F4   (L2_SLABS*1536)   // 98304 float4
#define TOT_F4  (L1_F4 + L2_F4)

__device__ float4 g_wts[TOT_F4];   // L1 blob | L2 blob, fragment-ordered tf32

// ---- smem layout (float offsets) ----
#define OFF_HA1 0
#define SZ_HA1  (2*L1_SLABS*32*4)            // 8448
#define OFF_HA2 (OFF_HA1 + SZ_HA1)
#define SZ_HA2  (2*32*32*4)                  // 8192
#define OFF_HF1 (OFF_HA2 + SZ_HA2)
#define OFF_HF2 (OFF_HF1 + NROWS*HFS)
#define OFF_B1  (OFF_HF2 + NROWS*HFS)
#define OFF_B2  (OFF_B1 + 2*G3)
#define OFF_WD  (OFF_B2 + 2*G3)
#define OFF_BD  (OFF_WD + UNITS*5)
#define OFF_PART (OFF_BD + 8)
#define OFF_QP  (OFF_PART + 16*160)
#define SMEM_FLOATS (OFF_QP + NROWS*128)
#define SMEM_BYTES  (SMEM_FLOATS*4)

// ---------------------------------------------------------------------------
__device__ __forceinline__ float f2tf(float f){
    uint32_t r; asm("cvt.rna.tf32.f32 %0, %1;" : "=r"(r) : "f"(f));
    return __uint_as_float(r);
}

__device__ __forceinline__ void mma_t(float (&c)[4], const uint4& a, uint32_t b0, uint32_t b1){
    asm volatile(
        "mma.sync.aligned.m16n8k8.row.col.f32.tf32.tf32.f32 "
        "{%0,%1,%2,%3},{%4,%5,%6,%7},{%8,%9},{%0,%1,%2,%3};\n"
        : "+f"(c[0]), "+f"(c[1]), "+f"(c[2]), "+f"(c[3])
        : "r"(a.x), "r"(a.y), "r"(a.z), "r"(a.w), "r"(b0), "r"(b1));
}

__device__ __forceinline__ float sigf(float x){
    float e = __expf(-x);
    return __fdividef(1.f, 1.f + e);
}
__device__ __forceinline__ float tanhf_(float x){
    float e = __expf(2.f * x);
    return 1.f - __fdividef(2.f, e + 1.f);
}

// One k8-slab of one gate for this warp's 16 units: 1 LDG.128, 4 mma.
// uint4 b_ = {tt0:k(lc), tt0:k(lc+4), tt1:k(lc), tt1:k(lc+4)}
#define GATE_SLAB(ACC, Bq, a0, a1) do {                    \
    uint4 b_ = __ldg((Bq));                                \
    mma_t(ACC[0][0], a0, b_.x, b_.y);                      \
    mma_t(ACC[1][0], a1, b_.x, b_.y);                      \
    mma_t(ACC[0][1], a0, b_.z, b_.w);                      \
    mma_t(ACC[1][1], a1, b_.z, b_.w);                      \
} while (0)

// ---------------------------------------------------------------------------
// prep: permute U1|W1pad -> L1 blob, W2|U2 -> L2 blob, tf32-rounded.
// float4 index = slab*1536 + g*512 + t2*256 + w*32 + lane; j in 0..3:
//   tt=2*t2+(j>>1), q=j&1, k = slab*8 + (lane&3) + 4q,
//   col = g*256 + w*32 + tt*8 + (lane>>2).
__global__ void prep_kernel(const float* __restrict__ W1, const float* __restrict__ U1,
                            const float* __restrict__ W2, const float* __restrict__ U2){
    for (int idx = blockIdx.x*blockDim.x + threadIdx.x; idx < TOT_F4;
         idx += gridDim.x*blockDim.x){
        int li   = (idx < L1_F4) ? idx : idx - L1_F4;
        int lane = li & 31;
        int w    = (li >> 5) & 7;
        int t2   = (li >> 8) & 1;
        int g    = (li >> 9) % 3;
        int slab = (li >> 9) / 3;
        int lc = lane & 3, lr = lane >> 2;
        float v[4];
        #pragma unroll
        for (int j = 0; j < 4; j++){
            int q  = j & 1;
            int tt = t2*2 + (j >> 1);
            int col = g*256 + w*32 + tt*8 + lr;
            int kk  = lc + 4*q;
            float s;
            if (idx < L1_F4){
                if (slab < 32) s = U1[(slab*8 + kk)*G3 + col];
                else           s = (kk < 6) ? W1[kk*G3 + col] : 0.f;
            } else {
                if (slab < 32) s = W2[(slab*8 + kk)*G3 + col];
                else           s = U2[((slab-32)*8 + kk)*G3 + col];
            }
            uint32_t r; asm("cvt.rna.tf32.f32 %0, %1;" : "=r"(r) : "f"(s));
            v[j] = __uint_as_float(r);
        }
        g_wts[idx] = make_float4(v[0], v[1], v[2], v[3]);
    }
}

// ---------------------------------------------------------------------------
__global__ void __launch_bounds__(NTHREADS, 1)
gru_kernel(const float* __restrict__ inputs, const float* __restrict__ gb1,
           const float* __restrict__ gb2, const float* __restrict__ gWd,
           const float* __restrict__ gbd, float* __restrict__ out){
    extern __shared__ __align__(16) float sm[];
    float* hF1 = sm + OFF_HF1;
    float* hF2 = sm + OFF_HF2;
    float* b1s = sm + OFF_B1;
    float* b2s = sm + OFF_B2;
    float* wds = sm + OFF_WD;
    float* bds = sm + OFF_BD;
    float* part= sm + OFF_PART;
    float* qpre= sm + OFF_QP;

    const int tid  = threadIdx.x;
    const int lane = tid & 31;
    const int warp = tid >> 5;         // 0..15
    const int lr   = lane >> 2;
    const int lc   = lane & 3;
    const int u0   = warp * 16;        // this warp's 16 units
    const int row0 = blockIdx.x * NROWS;
    // per-warp B-blob offset: t2 = warp&1, w = warp>>1
    const int wB   = ((warp & 1) << 8) + ((warp >> 1) << 5) + lane;

    // init persistent smem
    for (int i = tid; i < 2*G3;    i += NTHREADS) b1s[i] = gb1[i];
    for (int i = tid; i < 2*G3;    i += NTHREADS) b2s[i] = gb2[i];
    for (int i = tid; i < UNITS*5; i += NTHREADS) wds[i] = gWd[i];
    if (tid < 5) bds[tid] = gbd[tid];
    for (int i = tid; i < SZ_HA1;    i += NTHREADS) sm[OFF_HA1 + i] = 0.f;
    for (int i = tid; i < SZ_HA2;    i += NTHREADS) sm[OFF_HA2 + i] = 0.f;
    for (int i = tid; i < NROWS*HFS; i += NTHREADS){ hF1[i] = 0.f; hF2[i] = 0.f; }
    // prefetch decode Q: qpre[row*128 + s] = inputs[grow, 64+s, 0], s=0..126
    for (int i = tid; i < NROWS*127; i += NTHREADS){
        int row = i / 127, s = i % 127;
        qpre[row*128 + s] = inputs[((size_t)(row0 + row)*192 + WARM + s)*6];
    }
    __syncthreads();

    // assemble x_0 (warmup) into hA1 slab 32
    if (tid < NROWS){
        int row = tid;
        const float* ip = inputs + ((size_t)(row0 + row)*192 + 0)*6;
        int m = row >> 4, r = row & 15, rl = r & 7, hi2 = r >> 3;
        #pragma unroll
        for (int k = 0; k < 6; k++){
            int lcc = k & 3, q = k >> 2;
            sm[OFF_HA1 + ((m*L1_SLABS + 32)*32 + rl*4 + lcc)*4 + hi2 + 2*q] = f2tf(ip[k]);
        }
    }
    __syncthreads();

    const uint4* hA1u = (const uint4*)(sm + OFF_HA1);
    const uint4* hA2u = (const uint4*)(sm + OFF_HA2);
    const uint4* B1b  = ((const uint4*)g_wts) + wB;
    const uint4* B2b  = ((const uint4*)g_wts) + L1_F4 + wB;

    float az[2][2][4], ar[2][2][4], axh[2][2][4], arh[2][2][4];
    float hn[2][2][4];

    for (int t = 0; t < TSTEPS; t++){
        // ---- layer 1 GEMMs (x_t already staged in hA1 slab 32) ----
        #pragma unroll
        for (int m = 0; m < 2; m++)
            #pragma unroll
            for (int tt = 0; tt < 2; tt++)
                #pragma unroll
                for (int c = 0; c < 4; c++){
                    az[m][tt][c]=0.f; ar[m][tt][c]=0.f;
                    axh[m][tt][c]=0.f; arh[m][tt][c]=0.f;
                }
        for (int s = 0; s < 32; s++){
            uint4 a0 = hA1u[(0*L1_SLABS + s)*32 + lane];
            uint4 a1 = hA1u[(1*L1_SLABS + s)*32 + lane];
            const uint4* Bs = B1b + s*1536;
            GATE_SLAB(az,  Bs,        a0, a1);
            GATE_SLAB(ar,  Bs + 512,  a0, a1);
            GATE_SLAB(arh, Bs + 1024, a0, a1);
        }
        {   // x slab (32): z,r merged with h-side; h-gate -> xh
            uint4 a0 = hA1u[(0*L1_SLABS + 32)*32 + lane];
            uint4 a1 = hA1u[(1*L1_SLABS + 32)*32 + lane];
            const uint4* Bs = B1b + 32*1536;
            GATE_SLAB(az,  Bs,        a0, a1);
            GATE_SLAB(ar,  Bs + 512,  a0, a1);
            GATE_SLAB(axh, Bs + 1024, a0, a1);
        }

        // ---- layer 1 gate math (state in hF1, full fp32) ----
        #pragma unroll
        for (int tt = 0; tt < 2; tt++)
            #pragma unroll
            for (int cc = 0; cc < 2; cc++){
                int uc = u0 + tt*8 + 2*lc + cc;
                float bz  = b1s[uc]       + b1s[G3 + uc];
                float br  = b1s[256 + uc] + b1s[G3 + 256 + uc];
                float bxh = b1s[512 + uc];
                float brh = b1s[G3 + 512 + uc];
                #pragma unroll
                for (int m = 0; m < 2; m++)
                    #pragma unroll
                    for (int hi = 0; hi < 2; hi++){
                        int c = hi*2 + cc;
                        int row = 16*m + lr + 8*hi;
                        float z = sigf(az[m][tt][c] + bz);
                        float r = sigf(ar[m][tt][c] + br);
                        float hh = tanhf_(axh[m][tt][c] + bxh + r*(arh[m][tt][c] + brh));
                        float ho = hF1[row*HFS + uc];
                        float v  = z*ho + (1.f - z)*hh;
                        hF1[row*HFS + uc] = v;
                        hn[m][tt][c] = v;
                    }
            }
        __syncthreads();                                   // S2 (hA1 GEMM reads done)
        #pragma unroll
        for (int tt = 0; tt < 2; tt++)
            #pragma unroll
            for (int cc = 0; cc < 2; cc++){
                int kc = 2*lc + cc, lcc = kc & 3, q = kc >> 2;
                #pragma unroll
                for (int m = 0; m < 2; m++)
                    #pragma unroll
                    for (int hi = 0; hi < 2; hi++)
                        sm[OFF_HA1 + ((m*L1_SLABS + warp*2 + tt)*32 + lr*4 + lcc)*4
                           + hi + 2*q] = f2tf(hn[m][tt][hi*2 + cc]);
            }
        __syncthreads();                                   // S3

        // ---- layer 2 GEMMs: slabs 0-31 A=h1new (W2, h->xh); 32-63 A=h2 (U2, h->rh)
        #pragma unroll
        for (int m = 0; m < 2; m++)
            #pragma unroll
            for (int tt = 0; tt < 2; tt++)
                #pragma unroll
                for (int c = 0; c < 4; c++){
                    az[m][tt][c]=0.f; ar[m][tt][c]=0.f;
                    axh[m][tt][c]=0.f; arh[m][tt][c]=0.f;
                }
        for (int s = 0; s < 32; s++){
            uint4 a0 = hA1u[(0*L1_SLABS + s)*32 + lane];
            uint4 a1 = hA1u[(1*L1_SLABS + s)*32 + lane];
            const uint4* Bs = B2b + s*1536;
            GATE_SLAB(az,  Bs,        a0, a1);
            GATE_SLAB(ar,  Bs + 512,  a0, a1);
            GATE_SLAB(axh, Bs + 1024, a0, a1);
        }
        for (int s = 32; s < 64; s++){
            uint4 a0 = hA2u[(0*32 + (s-32))*32 + lane];
            uint4 a1 = hA2u[(1*32 + (s-32))*32 + lane];
            const uint4* Bs = B2b + s*1536;
            GATE_SLAB(az,  Bs,        a0, a1);
            GATE_SLAB(ar,  Bs + 512,  a0, a1);
            GATE_SLAB(arh, Bs + 1024, a0, a1);
        }

        // ---- layer 2 gate math + pred partials ----
        float ps[4][5];
        #pragma unroll
        for (int ri = 0; ri < 4; ri++)
            #pragma unroll
            for (int o = 0; o < 5; o++) ps[ri][o] = 0.f;

        #pragma unroll
        for (int tt = 0; tt < 2; tt++)
            #pragma unroll
            for (int cc = 0; cc < 2; cc++){
                int uc = u0 + tt*8 + 2*lc + cc;
                float bz  = b2s[uc]       + b2s[G3 + uc];
                float br  = b2s[256 + uc] + b2s[G3 + 256 + uc];
                float bxh = b2s[512 + uc];
                float brh = b2s[G3 + 512 + uc];
                float wdv[5];
                #pragma unroll
                for (int o = 0; o < 5; o++) wdv[o] = wds[uc*5 + o];
                #pragma unroll
                for (int m = 0; m < 2; m++)
                    #pragma unroll
                    for (int hi = 0; hi < 2; hi++){
                        int c = hi*2 + cc;
                        int row = 16*m + lr + 8*hi;
                        float z = sigf(az[m][tt][c] + bz);
                        float r = sigf(ar[m][tt][c] + br);
                        float hh = tanhf_(axh[m][tt][c] + bxh + r*(arh[m][tt][c] + brh));
                        float ho = hF2[row*HFS + uc];
                        float v  = z*ho + (1.f - z)*hh;
                        hF2[row*HFS + uc] = v;
                        hn[m][tt][c] = v;
                        int ri = 2*m + hi;   // row = lr + 8*ri
                        #pragma unroll
                        for (int o = 0; o < 5; o++) ps[ri][o] += v * wdv[o];
                    }
            }
        // reduce pred partials over the 4 lc lanes
        #pragma unroll
        for (int ri = 0; ri < 4; ri++)
            #pragma unroll
            for (int o = 0; o < 5; o++){
                ps[ri][o] += __shfl_xor_sync(0xffffffffu, ps[ri][o], 1);
                ps[ri][o] += __shfl_xor_sync(0xffffffffu, ps[ri][o], 2);
            }
        if (lc == 0){
            #pragma unroll
            for (int ri = 0; ri < 4; ri++)
                #pragma unroll
                for (int o = 0; o < 5; o++)
                    part[warp*160 + (lr + 8*ri)*5 + o] = ps[ri][o];
        }
        __syncthreads();                                   // S4 (hA2 reads + part done)

        // write h2new to hA2
        #pragma unroll
        for (int tt = 0; tt < 2; tt++)
            #pragma unroll
            for (int cc = 0; cc < 2; cc++){
                int kc = 2*lc + cc, lcc = kc & 3, q = kc >> 2;
                #pragma unroll
                for (int m = 0; m < 2; m++)
                    #pragma unroll
                    for (int hi = 0; hi < 2; hi++)
                        sm[OFF_HA2 + ((m*32 + warp*2 + tt)*32 + lr*4 + lcc)*4
                           + hi + 2*q] = f2tf(hn[m][tt][hi*2 + cc]);
            }

        // final pred reduce + output + stage decode-x (k=1..5) for t+1
        if (tid < 160){
            int row = tid / 5, o = tid % 5;
            float s = bds[o];
            #pragma unroll
            for (int w = 0; w < 16; w++) s += part[w*160 + tid];
            int grow = row0 + row;
            int tout = (t < WARM) ? t : t + 1;
            out[(size_t)grow*960 + tout*5 + o] = s;
            if (t == WARM - 1) out[(size_t)grow*960 + WARM*5 + o] = s;
            if (t + 1 >= WARM && t + 1 < TSTEPS){
                int k = o + 1;                 // pred feeds x[1..5]
                int m = row >> 4, r = row & 15, rl = r & 7, hi2 = r >> 3;
                int lcc = k & 3, q = k >> 2;
                sm[OFF_HA1 + ((m*L1_SLABS + 32)*32 + rl*4 + lcc)*4 + hi2 + 2*q] = f2tf(s);
            }
        }
        // stage x[k=0] (Q) or full warmup x for t+1
        if (tid < NROWS && t + 1 < TSTEPS){
            int row = tid;
            int m = row >> 4, r = row & 15, rl = r & 7, hi2 = r >> 3;
            if (t + 1 < WARM){
                const float* ip = inputs + ((size_t)(row0 + row)*192 + (t + 1))*6;
                #pragma unroll
                for (int k = 0; k < 6; k++){
                    int lcc = k & 3, q = k >> 2;
                    sm[OFF_HA1 + ((m*L1_SLABS + 32)*32 + rl*4 + lcc)*4 + hi2 + 2*q] = f2tf(ip[k]);
                }
            } else {
                float qv = qpre[row*128 + (t + 1 - WARM)];
                sm[OFF_HA1 + ((m*L1_SLABS + 32)*32 + rl*4 + 0)*4 + hi2] = f2tf(qv);
            }
        }
        __syncthreads();                                   // S5
    }
}

// ---------------------------------------------------------------------------
extern "C" void kernel_launch(void* const* d_in, const int* in_sizes, int n_in,
                              void* d_out, int out_size) {
    (void)in_sizes; (void)n_in; (void)out_size;
    const float* inputs = (const float*)d_in[0];
    const float* W1 = (const float*)d_in[1];
    const float* U1 = (const float*)d_in[2];
    const float* b1 = (const float*)d_in[3];
    const float* W2 = (const float*)d_in[4];
    const float* U2 = (const float*)d_in[5];
    const float* b2 = (const float*)d_in[6];
    const float* Wd = (const float*)d_in[7];
    const float* bd = (const float*)d_in[8];
    float* out = (float*)d_out;

    cudaFuncSetAttribute(gru_kernel, cudaFuncAttributeMaxDynamicSharedMemorySize,
                         SMEM_BYTES);
    prep_kernel<<<(TOT_F4 + 255)/256, 256>>>(W1, U1, W2, U2);
    gru_kernel<<<NCTA, NTHREADS, SMEM_BYTES>>>(inputs, b1, b2, Wd, bd, out);
}

// round 5
// speedup vs baseline: 1.1495x; 1.0461x over previous
#include <cuda_runtime.h>
#include <cstdint>

// ---------------------------------------------------------------------------
// 2-layer GRU (256 units), B=4096, 64 warmup + 127 closed-loop decode steps.
// Persistent kernel: 128 CTAs x 32 rows x 512 threads (16 warps x 16 units),
// tf32 mma.sync. 3 barriers/step, double-buffered h1 A-tiles, chained
// B-prefetch so the weight stream never stalls a segment start.
// ---------------------------------------------------------------------------

#define UNITS   256
#define G3      768
#define NROWS   32
#define NCTA    128
#define NTHREADS 512
#define TSTEPS  191
#define WARM    64
#define HFS     260

#define L1_SLABS 33
#define L1_F4   (L1_SLABS*1536)   // 50688 float4
#define L2_F4   (64*1536)         // 98304 float4
#define TOT_F4  (L1_F4 + L2_F4)

__device__ float4 g_wts[TOT_F4];   // L1 blob | L2 blob, fragment-ordered tf32

// ---- smem layout (float offsets) ----
#define SZ_HA1  (2*L1_SLABS*32*4)            // 8448 per buffer
#define OFF_HA1 0                            // two buffers
#define OFF_HA2 (OFF_HA1 + 2*SZ_HA1)         // 16896
#define SZ_HA2  (2*32*32*4)                  // 8192 (single buffer)
#define OFF_HF1 (OFF_HA2 + SZ_HA2)
#define OFF_HF2 (OFF_HF1 + NROWS*HFS)
#define OFF_B1  (OFF_HF2 + NROWS*HFS)
#define OFF_B2  (OFF_B1 + 2*G3)
#define OFF_WD  (OFF_B2 + 2*G3)
#define OFF_BD  (OFF_WD + UNITS*5)
#define OFF_PART (OFF_BD + 8)
#define OFF_QP  (OFF_PART + 16*160)
#define SMEM_FLOATS (OFF_QP + NROWS*127)
#define SMEM_BYTES  (SMEM_FLOATS*4)

// ---------------------------------------------------------------------------
__device__ __forceinline__ float f2tf(float f){
    uint32_t r; asm("cvt.rna.tf32.f32 %0, %1;" : "=r"(r) : "f"(f));
    return __uint_as_float(r);
}

__device__ __forceinline__ void mma_t(float (&c)[4], const uint4& a, uint32_t b0, uint32_t b1){
    asm volatile(
        "mma.sync.aligned.m16n8k8.row.col.f32.tf32.tf32.f32 "
        "{%0,%1,%2,%3},{%4,%5,%6,%7},{%8,%9},{%0,%1,%2,%3};\n"
        : "+f"(c[0]), "+f"(c[1]), "+f"(c[2]), "+f"(c[3])
        : "r"(a.x), "r"(a.y), "r"(a.z), "r"(a.w), "r"(b0), "r"(b1));
}

__device__ __forceinline__ float sigf(float x){
    float e = __expf(-x);
    return __fdividef(1.f, 1.f + e);
}
__device__ __forceinline__ float tanhf_(float x){
    float e = __expf(2.f * x);
    return 1.f - __fdividef(2.f, e + 1.f);
}

// 4 mma for one gate, B fragment already in registers.
#define MMA_GATE(ACC, B4, a0, a1) do {                     \
    mma_t(ACC[0][0], a0, (B4).x, (B4).y);                  \
    mma_t(ACC[1][0], a1, (B4).x, (B4).y);                  \
    mma_t(ACC[0][1], a0, (B4).z, (B4).w);                  \
    mma_t(ACC[1][1], a1, (B4).z, (B4).w);                  \
} while (0)

#define ZERO_ACC do {                                      \
    _Pragma("unroll")                                      \
    for (int m_ = 0; m_ < 2; m_++)                         \
        _Pragma("unroll")                                  \
        for (int t_ = 0; t_ < 2; t_++)                     \
            _Pragma("unroll")                              \
            for (int c_ = 0; c_ < 4; c_++){                \
                az[m_][t_][c_]=0.f; ar[m_][t_][c_]=0.f;    \
                axh[m_][t_][c_]=0.f; arh[m_][t_][c_]=0.f;  \
            }                                              \
} while (0)

// ---------------------------------------------------------------------------
// prep: permute U1|W1pad -> L1 blob, W2|U2 -> L2 blob, tf32-rounded.
// float4 index = slab*1536 + g*512 + t2*256 + w*32 + lane; j in 0..3:
//   tt=2*t2+(j>>1), q=j&1, k = slab*8 + (lane&3) + 4q,
//   col = g*256 + w*32 + tt*8 + (lane>>2).
__global__ void prep_kernel(const float* __restrict__ W1, const float* __restrict__ U1,
                            const float* __restrict__ W2, const float* __restrict__ U2){
    for (int idx = blockIdx.x*blockDim.x + threadIdx.x; idx < TOT_F4;
         idx += gridDim.x*blockDim.x){
        int li   = (idx < L1_F4) ? idx : idx - L1_F4;
        int lane = li & 31;
        int w    = (li >> 5) & 7;
        int t2   = (li >> 8) & 1;
        int g    = (li >> 9) % 3;
        int slab = (li >> 9) / 3;
        int lc = lane & 3, lr = lane >> 2;
        float v[4];
        #pragma unroll
        for (int j = 0; j < 4; j++){
            int q  = j & 1;
            int tt = t2*2 + (j >> 1);
            int col = g*256 + w*32 + tt*8 + lr;
            int kk  = lc + 4*q;
            float s;
            if (idx < L1_F4){
                if (slab < 32) s = U1[(slab*8 + kk)*G3 + col];
                else           s = (kk < 6) ? W1[kk*G3 + col] : 0.f;
            } else {
                if (slab < 32) s = W2[(slab*8 + kk)*G3 + col];
                else           s = U2[((slab-32)*8 + kk)*G3 + col];
            }
            uint32_t r; asm("cvt.rna.tf32.f32 %0, %1;" : "=r"(r) : "f"(s));
            v[j] = __uint_as_float(r);
        }
        g_wts[idx] = make_float4(v[0], v[1], v[2], v[3]);
    }
}

// ---------------------------------------------------------------------------
__global__ void __launch_bounds__(NTHREADS, 1)
gru_kernel(const float* __restrict__ inputs, const float* __restrict__ gb1,
           const float* __restrict__ gb2, const float* __restrict__ gWd,
           const float* __restrict__ gbd, float* __restrict__ out){
    extern __shared__ __align__(16) float sm[];
    float* hF1 = sm + OFF_HF1;
    float* hF2 = sm + OFF_HF2;
    float* b1s = sm + OFF_B1;
    float* b2s = sm + OFF_B2;
    float* wds = sm + OFF_WD;
    float* bds = sm + OFF_BD;
    float* part= sm + OFF_PART;
    float* qpre= sm + OFF_QP;

    const int tid  = threadIdx.x;
    const int lane = tid & 31;
    const int warp = tid >> 5;         // 0..15
    const int lr   = lane >> 2;
    const int lc   = lane & 3;
    const int u0   = warp * 16;        // this warp's 16 units
    const int row0 = blockIdx.x * NROWS;
    // per-warp B-blob offset: t2 = warp&1, w = warp>>1
    const int wB   = ((warp & 1) << 8) + ((warp >> 1) << 5) + lane;

    // init persistent smem
    for (int i = tid; i < 2*G3;    i += NTHREADS) b1s[i] = gb1[i];
    for (int i = tid; i < 2*G3;    i += NTHREADS) b2s[i] = gb2[i];
    for (int i = tid; i < UNITS*5; i += NTHREADS) wds[i] = gWd[i];
    if (tid < 5) bds[tid] = gbd[tid];
    for (int i = tid; i < 2*SZ_HA1; i += NTHREADS) sm[OFF_HA1 + i] = 0.f;
    for (int i = tid; i < SZ_HA2;   i += NTHREADS) sm[OFF_HA2 + i] = 0.f;
    for (int i = tid; i < NROWS*HFS; i += NTHREADS){ hF1[i] = 0.f; hF2[i] = 0.f; }
    // prefetch decode Q: qpre[row*127 + s] = inputs[grow, 64+s, 0], s=0..126
    for (int i = tid; i < NROWS*127; i += NTHREADS){
        int row = i / 127, s = i % 127;
        qpre[i] = inputs[((size_t)(row0 + row)*192 + WARM + s)*6];
    }
    __syncthreads();

    // assemble x_0 (warmup) into hA1 buffer 0, slab 32
    if (tid < NROWS){
        int row = tid;
        const float* ip = inputs + ((size_t)(row0 + row)*192 + 0)*6;
        int m = row >> 4, r = row & 15, rl = r & 7, hi2 = r >> 3;
        #pragma unroll
        for (int k = 0; k < 6; k++){
            int lcc = k & 3, q = k >> 2;
            sm[OFF_HA1 + ((m*L1_SLABS + 32)*32 + rl*4 + lcc)*4 + hi2 + 2*q] = f2tf(ip[k]);
        }
    }
    __syncthreads();

    const uint4* hA2u = (const uint4*)(sm + OFF_HA2);
    const uint4* B1b  = ((const uint4*)g_wts) + wB;
    const uint4* B2b  = ((const uint4*)g_wts) + L1_F4 + wB;

    float az[2][2][4], ar[2][2][4], axh[2][2][4], arh[2][2][4];
    float hn[2][2][4];

    // prologue: prefetch GEMM1 slab 0 B fragments
    uint4 pbz = __ldg(B1b), pbr = __ldg(B1b + 512), pbh = __ldg(B1b + 1024);

    for (int t = 0; t < TSTEPS; t++){
        const int p = t & 1;
        const uint4* hAr = (const uint4*)(sm + OFF_HA1 + p*SZ_HA1);       // read buf
        float*       hWf = sm + OFF_HA1 + (1-p)*SZ_HA1;                   // write buf
        const uint4* hAw = (const uint4*)hWf;

        // ================= GEMM1: h1_old (slabs 0..31) + x (slab 32) ======
        ZERO_ACC;
        #pragma unroll 2
        for (int s = 0; s < 32; s++){
            uint4 a0 = hAr[s*32 + lane];
            uint4 a1 = hAr[(L1_SLABS + s)*32 + lane];
            uint4 cz = pbz, cr = pbr, ch = pbh;
            const uint4* Bn = B1b + (s+1)*1536;
            pbz = __ldg(Bn); pbr = __ldg(Bn + 512); pbh = __ldg(Bn + 1024);
            MMA_GATE(az,  cz, a0, a1);
            MMA_GATE(ar,  cr, a0, a1);
            MMA_GATE(arh, ch, a0, a1);
        }
        {   // x slab; chain prefetch -> GEMM2a (U2 slab 32)
            uint4 a0 = hAr[32*32 + lane];
            uint4 a1 = hAr[(L1_SLABS + 32)*32 + lane];
            uint4 cz = pbz, cr = pbr, ch = pbh;
            const uint4* Bn = B2b + 32*1536;
            pbz = __ldg(Bn); pbr = __ldg(Bn + 512); pbh = __ldg(Bn + 1024);
            MMA_GATE(az,  cz, a0, a1);
            MMA_GATE(ar,  cr, a0, a1);
            MMA_GATE(axh, ch, a0, a1);
        }

        // ---- layer 1 gate math (state in hF1, full fp32) ----
        #pragma unroll
        for (int tt = 0; tt < 2; tt++)
            #pragma unroll
            for (int cc = 0; cc < 2; cc++){
                int uc = u0 + tt*8 + 2*lc + cc;
                float bz  = b1s[uc]       + b1s[G3 + uc];
                float br  = b1s[256 + uc] + b1s[G3 + 256 + uc];
                float bxh = b1s[512 + uc];
                float brh = b1s[G3 + 512 + uc];
                #pragma unroll
                for (int m = 0; m < 2; m++)
                    #pragma unroll
                    for (int hi = 0; hi < 2; hi++){
                        int c = hi*2 + cc;
                        int row = 16*m + lr + 8*hi;
                        float z = sigf(az[m][tt][c] + bz);
                        float r = sigf(ar[m][tt][c] + br);
                        float hh = tanhf_(axh[m][tt][c] + bxh + r*(arh[m][tt][c] + brh));
                        float ho = hF1[row*HFS + uc];
                        float v  = z*ho + (1.f - z)*hh;
                        hF1[row*HFS + uc] = v;
                        hn[m][tt][c] = v;
                    }
            }
        // store h1_new into write buffer (no barrier needed: nobody reads it
        // until after B1)
        #pragma unroll
        for (int tt = 0; tt < 2; tt++)
            #pragma unroll
            for (int cc = 0; cc < 2; cc++){
                int kc = 2*lc + cc, lcc = kc & 3, q = kc >> 2;
                #pragma unroll
                for (int m = 0; m < 2; m++)
                    #pragma unroll
                    for (int hi = 0; hi < 2; hi++)
                        hWf[((m*L1_SLABS + warp*2 + tt)*32 + lr*4 + lcc)*4
                            + hi + 2*q] = f2tf(hn[m][tt][hi*2 + cc]);
            }

        // ================= GEMM2a: h2_old @ U2 (blob slabs 32..63) ========
        ZERO_ACC;
        #pragma unroll 2
        for (int s = 0; s < 32; s++){
            uint4 a0 = hA2u[s*32 + lane];
            uint4 a1 = hA2u[(32 + s)*32 + lane];
            uint4 cz = pbz, cr = pbr, ch = pbh;
            const uint4* Bn = (s < 31) ? (B2b + (33 + s)*1536) : B2b;  // chain -> W2 slab 0
            pbz = __ldg(Bn); pbr = __ldg(Bn + 512); pbh = __ldg(Bn + 1024);
            MMA_GATE(az,  cz, a0, a1);
            MMA_GATE(ar,  cr, a0, a1);
            MMA_GATE(arh, ch, a0, a1);
        }
        __syncthreads();                                   // B1: h1_new visible

        // ================= GEMM2b: h1_new @ W2 (blob slabs 0..31) =========
        #pragma unroll 2
        for (int s = 0; s < 32; s++){
            uint4 a0 = hAw[s*32 + lane];
            uint4 a1 = hAw[(L1_SLABS + s)*32 + lane];
            uint4 cz = pbz, cr = pbr, ch = pbh;
            const uint4* Bn = (s < 31) ? (B2b + (s+1)*1536) : B1b;     // chain -> next GEMM1
            pbz = __ldg(Bn); pbr = __ldg(Bn + 512); pbh = __ldg(Bn + 1024);
            MMA_GATE(az,  cz, a0, a1);
            MMA_GATE(ar,  cr, a0, a1);
            MMA_GATE(axh, ch, a0, a1);
        }

        // ---- layer 2 gate math + h2 store + pred partials ----
        float ps[4][5];
        #pragma unroll
        for (int ri = 0; ri < 4; ri++)
            #pragma unroll
            for (int o = 0; o < 5; o++) ps[ri][o] = 0.f;

        #pragma unroll
        for (int tt = 0; tt < 2; tt++)
            #pragma unroll
            for (int cc = 0; cc < 2; cc++){
                int uc = u0 + tt*8 + 2*lc + cc;
                float bz  = b2s[uc]       + b2s[G3 + uc];
                float br  = b2s[256 + uc] + b2s[G3 + 256 + uc];
                float bxh = b2s[512 + uc];
                float brh = b2s[G3 + 512 + uc];
                float wdv[5];
                #pragma unroll
                for (int o = 0; o < 5; o++) wdv[o] = wds[uc*5 + o];
                #pragma unroll
                for (int m = 0; m < 2; m++)
                    #pragma unroll
                    for (int hi = 0; hi < 2; hi++){
                        int c = hi*2 + cc;
                        int row = 16*m + lr + 8*hi;
                        float z = sigf(az[m][tt][c] + bz);
                        float r = sigf(ar[m][tt][c] + br);
                        float hh = tanhf_(axh[m][tt][c] + bxh + r*(arh[m][tt][c] + brh));
                        float ho = hF2[row*HFS + uc];
                        float v  = z*ho + (1.f - z)*hh;
                        hF2[row*HFS + uc] = v;
                        hn[m][tt][c] = v;
                        int ri = 2*m + hi;   // row = lr + 8*ri
                        #pragma unroll
                        for (int o = 0; o < 5; o++) ps[ri][o] += v * wdv[o];
                    }
            }
        // store h2_new to hA2 (WAR-safe: all hA2 reads happened before B1)
        #pragma unroll
        for (int tt = 0; tt < 2; tt++)
            #pragma unroll
            for (int cc = 0; cc < 2; cc++){
                int kc = 2*lc + cc, lcc = kc & 3, q = kc >> 2;
                #pragma unroll
                for (int m = 0; m < 2; m++)
                    #pragma unroll
                    for (int hi = 0; hi < 2; hi++)
                        sm[OFF_HA2 + ((m*32 + warp*2 + tt)*32 + lr*4 + lcc)*4
                           + hi + 2*q] = f2tf(hn[m][tt][hi*2 + cc]);
            }
        // reduce pred partials over the 4 lc lanes
        #pragma unroll
        for (int ri = 0; ri < 4; ri++)
            #pragma unroll
            for (int o = 0; o < 5; o++){
                ps[ri][o] += __shfl_xor_sync(0xffffffffu, ps[ri][o], 1);
                ps[ri][o] += __shfl_xor_sync(0xffffffffu, ps[ri][o], 2);
            }
        if (lc == 0){
            #pragma unroll
            for (int ri = 0; ri < 4; ri++)
                #pragma unroll
                for (int o = 0; o < 5; o++)
                    part[warp*160 + (lr + 8*ri)*5 + o] = ps[ri][o];
        }
        __syncthreads();                                   // B2: part + h2 visible

        // final pred reduce + output + stage decode-x (k=1..5) for t+1
        if (tid < 160){
            int row = tid / 5, o = tid % 5;
            float s = bds[o];
            #pragma unroll
            for (int w = 0; w < 16; w++) s += part[w*160 + tid];
            int grow = row0 + row;
            int tout = (t < WARM) ? t : t + 1;
            out[(size_t)grow*960 + tout*5 + o] = s;
            if (t == WARM - 1) out[(size_t)grow*960 + WARM*5 + o] = s;
            if (t + 1 >= WARM && t + 1 < TSTEPS){
                int k = o + 1;                 // pred feeds x[1..5]
                int m = row >> 4, r = row & 15, rl = r & 7, hi2 = r >> 3;
                int lcc = k & 3, q = k >> 2;
                hWf[((m*L1_SLABS + 32)*32 + rl*4 + lcc)*4 + hi2 + 2*q] = f2tf(s);
            }
        }
        // stage x[k=0] (Q) or full warmup x for t+1 (into write buffer)
        if (tid < NROWS && t + 1 < TSTEPS){
            int row = tid;
            int m = row >> 4, r = row & 15, rl = r & 7, hi2 = r >> 3;
            if (t + 1 < WARM){
                const float* ip = inputs + ((size_t)(row0 + row)*192 + (t + 1))*6;
                #pragma unroll
                for (int k = 0; k < 6; k++){
                    int lcc = k & 3, q = k >> 2;
                    hWf[((m*L1_SLABS + 32)*32 + rl*4 + lcc)*4 + hi2 + 2*q] = f2tf(ip[k]);
                }
            } else {
                float qv = qpre[row*127 + (t + 1 - WARM)];
                hWf[((m*L1_SLABS + 32)*32 + rl*4 + 0)*4 + hi2] = f2tf(qv);
            }
        }
        __syncthreads();                                   // B3: x_{t+1} visible
    }
}

// ---------------------------------------------------------------------------
extern "C" void kernel_launch(void* const* d_in, const int* in_sizes, int n_in,
                              void* d_out, int out_size) {
    (void)in_sizes; (void)n_in; (void)out_size;
    const float* inputs = (const float*)d_in[0];
    const float* W1 = (const float*)d_in[1];
    const float* U1 = (const float*)d_in[2];
    const float* b1 = (const float*)d_in[3];
    const float* W2 = (const float*)d_in[4];
    const float* U2 = (const float*)d_in[5];
    const float* b2 = (const float*)d_in[6];
    const float* Wd = (const float*)d_in[7];
    const float* bd = (const float*)d_in[8];
    float* out = (float*)d_out;

    cudaFuncSetAttribute(gru_kernel, cudaFuncAttributeMaxDynamicSharedMemorySize,
                         SMEM_BYTES);
    prep_kernel<<<(TOT_F4 + 255)/256, 256>>>(W1, U1, W2, U2);
    gru_kernel<<<NCTA, NTHREADS, SMEM_BYTES>>>(inputs, b1, b2, Wd, bd, out);
}

// round 6
// speedup vs baseline: 1.1510x; 1.0013x over previous
#include <cuda_runtime.h>
#include <cstdint>

// ---------------------------------------------------------------------------
// 2-layer GRU (256 units), B=4096, 64 warmup + 127 closed-loop decode steps.
// Persistent kernel: 128 CTAs x 32 rows x 512 threads (16 warps x 16 units),
// tf32 mma.sync. 3 barriers/step, double-buffered h1 A-tiles, chained
// B-prefetch so the weight stream never stalls a segment start.
// ---------------------------------------------------------------------------

#define UNITS   256
#define G3      768
#define NROWS   32
#define NCTA    128
#define NTHREADS 512
#define TSTEPS  191
#define WARM    64
#define HFS     260

#define L1_SLABS 33
#define L1_F4   (L1_SLABS*1536)   // 50688 float4
#define L2_F4   (64*1536)         // 98304 float4
#define TOT_F4  (L1_F4 + L2_F4)

__device__ float4 g_wts[TOT_F4];   // L1 blob | L2 blob, fragment-ordered tf32

// ---- smem layout (float offsets) ----
#define SZ_HA1  (2*L1_SLABS*32*4)            // 8448 per buffer
#define OFF_HA1 0                            // two buffers
#define OFF_HA2 (OFF_HA1 + 2*SZ_HA1)         // 16896
#define SZ_HA2  (2*32*32*4)                  // 8192 (single buffer)
#define OFF_HF1 (OFF_HA2 + SZ_HA2)
#define OFF_HF2 (OFF_HF1 + NROWS*HFS)
#define OFF_B1  (OFF_HF2 + NROWS*HFS)
#define OFF_B2  (OFF_B1 + 2*G3)
#define OFF_WD  (OFF_B2 + 2*G3)
#define OFF_BD  (OFF_WD + UNITS*5)
#define OFF_PART (OFF_BD + 8)
#define OFF_QP  (OFF_PART + 16*160)
#define SMEM_FLOATS (OFF_QP + NROWS*127)
#define SMEM_BYTES  (SMEM_FLOATS*4)

// ---------------------------------------------------------------------------
__device__ __forceinline__ float f2tf(float f){
    uint32_t r; asm("cvt.rna.tf32.f32 %0, %1;" : "=r"(r) : "f"(f));
    return __uint_as_float(r);
}

__device__ __forceinline__ void mma_t(float (&c)[4], const uint4& a, uint32_t b0, uint32_t b1){
    asm volatile(
        "mma.sync.aligned.m16n8k8.row.col.f32.tf32.tf32.f32 "
        "{%0,%1,%2,%3},{%4,%5,%6,%7},{%8,%9},{%0,%1,%2,%3};\n"
        : "+f"(c[0]), "+f"(c[1]), "+f"(c[2]), "+f"(c[3])
        : "r"(a.x), "r"(a.y), "r"(a.z), "r"(a.w), "r"(b0), "r"(b1));
}

__device__ __forceinline__ float sigf(float x){
    float e = __expf(-x);
    return __fdividef(1.f, 1.f + e);
}
__device__ __forceinline__ float tanhf_(float x){
    float e = __expf(2.f * x);
    return 1.f - __fdividef(2.f, e + 1.f);
}

// 4 mma for one gate, B fragment already in registers.
#define MMA_GATE(ACC, B4, a0, a1) do {                     \
    mma_t(ACC[0][0], a0, (B4).x, (B4).y);                  \
    mma_t(ACC[1][0], a1, (B4).x, (B4).y);                  \
    mma_t(ACC[0][1], a0, (B4).z, (B4).w);                  \
    mma_t(ACC[1][1], a1, (B4).z, (B4).w);                  \
} while (0)

#define ZERO_ACC do {                                      \
    _Pragma("unroll")                                      \
    for (int m_ = 0; m_ < 2; m_++)                         \
        _Pragma("unroll")                                  \
        for (int t_ = 0; t_ < 2; t_++)                     \
            _Pragma("unroll")                              \
            for (int c_ = 0; c_ < 4; c_++){                \
                az[m_][t_][c_]=0.f; ar[m_][t_][c_]=0.f;    \
                axh[m_][t_][c_]=0.f; arh[m_][t_][c_]=0.f;  \
            }                                              \
} while (0)

// ---------------------------------------------------------------------------
// prep: permute U1|W1pad -> L1 blob, W2|U2 -> L2 blob, tf32-rounded.
// float4 index = slab*1536 + g*512 + t2*256 + w*32 + lane; j in 0..3:
//   tt=2*t2+(j>>1), q=j&1, k = slab*8 + (lane&3) + 4q,
//   col = g*256 + w*32 + tt*8 + (lane>>2).
__global__ void prep_kernel(const float* __restrict__ W1, const float* __restrict__ U1,
                            const float* __restrict__ W2, const float* __restrict__ U2){
    for (int idx = blockIdx.x*blockDim.x + threadIdx.x; idx < TOT_F4;
         idx += gridDim.x*blockDim.x){
        int li   = (idx < L1_F4) ? idx : idx - L1_F4;
        int lane = li & 31;
        int w    = (li >> 5) & 7;
        int t2   = (li >> 8) & 1;
        int g    = (li >> 9) % 3;
        int slab = (li >> 9) / 3;
        int lc = lane & 3, lr = lane >> 2;
        float v[4];
        #pragma unroll
        for (int j = 0; j < 4; j++){
            int q  = j & 1;
            int tt = t2*2 + (j >> 1);
            int col = g*256 + w*32 + tt*8 + lr;
            int kk  = lc + 4*q;
            float s;
            if (idx < L1_F4){
                if (slab < 32) s = U1[(slab*8 + kk)*G3 + col];
                else           s = (kk < 6) ? W1[kk*G3 + col] : 0.f;
            } else {
                if (slab < 32) s = W2[(slab*8 + kk)*G3 + col];
                else           s = U2[((slab-32)*8 + kk)*G3 + col];
            }
            uint32_t r; asm("cvt.rna.tf32.f32 %0, %1;" : "=r"(r) : "f"(s));
            v[j] = __uint_as_float(r);
        }
        g_wts[idx] = make_float4(v[0], v[1], v[2], v[3]);
    }
}

// ---------------------------------------------------------------------------
__global__ void __launch_bounds__(NTHREADS, 1)
gru_kernel(const float* __restrict__ inputs, const float* __restrict__ gb1,
           const float* __restrict__ gb2, const float* __restrict__ gWd,
           const float* __restrict__ gbd, float* __restrict__ out){
    extern __shared__ __align__(16) float sm[];
    float* hF1 = sm + OFF_HF1;
    float* hF2 = sm + OFF_HF2;
    float* b1s = sm + OFF_B1;
    float* b2s = sm + OFF_B2;
    float* wds = sm + OFF_WD;
    float* bds = sm + OFF_BD;
    float* part= sm + OFF_PART;
    float* qpre= sm + OFF_QP;

    const int tid  = threadIdx.x;
    const int lane = tid & 31;
    const int warp = tid >> 5;         // 0..15
    const int lr   = lane >> 2;
    const int lc   = lane & 3;
    const int u0   = warp * 16;        // this warp's 16 units
    const int row0 = blockIdx.x * NROWS;
    // per-warp B-blob offset: t2 = warp&1, w = warp>>1
    const int wB   = ((warp & 1) << 8) + ((warp >> 1) << 5) + lane;

    // init persistent smem
    for (int i = tid; i < 2*G3;    i += NTHREADS) b1s[i] = gb1[i];
    for (int i = tid; i < 2*G3;    i += NTHREADS) b2s[i] = gb2[i];
    for (int i = tid; i < UNITS*5; i += NTHREADS) wds[i] = gWd[i];
    if (tid < 5) bds[tid] = gbd[tid];
    for (int i = tid; i < 2*SZ_HA1; i += NTHREADS) sm[OFF_HA1 + i] = 0.f;
    for (int i = tid; i < SZ_HA2;   i += NTHREADS) sm[OFF_HA2 + i] = 0.f;
    for (int i = tid; i < NROWS*HFS; i += NTHREADS){ hF1[i] = 0.f; hF2[i] = 0.f; }
    // prefetch decode Q: qpre[row*127 + s] = inputs[grow, 64+s, 0], s=0..126
    for (int i = tid; i < NROWS*127; i += NTHREADS){
        int row = i / 127, s = i % 127;
        qpre[i] = inputs[((size_t)(row0 + row)*192 + WARM + s)*6];
    }
    __syncthreads();

    // assemble x_0 (warmup) into hA1 buffer 0, slab 32
    if (tid < NROWS){
        int row = tid;
        const float* ip = inputs + ((size_t)(row0 + row)*192 + 0)*6;
        int m = row >> 4, r = row & 15, rl = r & 7, hi2 = r >> 3;
        #pragma unroll
        for (int k = 0; k < 6; k++){
            int lcc = k & 3, q = k >> 2;
            sm[OFF_HA1 + ((m*L1_SLABS + 32)*32 + rl*4 + lcc)*4 + hi2 + 2*q] = f2tf(ip[k]);
        }
    }
    __syncthreads();

    const uint4* hA2u = (const uint4*)(sm + OFF_HA2);
    const uint4* B1b  = ((const uint4*)g_wts) + wB;
    const uint4* B2b  = ((const uint4*)g_wts) + L1_F4 + wB;

    float az[2][2][4], ar[2][2][4], axh[2][2][4], arh[2][2][4];
    float hn[2][2][4];

    // prologue: prefetch GEMM1 slab 0 B fragments
    uint4 pbz = __ldg(B1b), pbr = __ldg(B1b + 512), pbh = __ldg(B1b + 1024);

    for (int t = 0; t < TSTEPS; t++){
        const int p = t & 1;
        const uint4* hAr = (const uint4*)(sm + OFF_HA1 + p*SZ_HA1);       // read buf
        float*       hWf = sm + OFF_HA1 + (1-p)*SZ_HA1;                   // write buf
        const uint4* hAw = (const uint4*)hWf;

        // ================= GEMM1: h1_old (slabs 0..31) + x (slab 32) ======
        ZERO_ACC;
        #pragma unroll 2
        for (int s = 0; s < 32; s++){
            uint4 a0 = hAr[s*32 + lane];
            uint4 a1 = hAr[(L1_SLABS + s)*32 + lane];
            uint4 cz = pbz, cr = pbr, ch = pbh;
            const uint4* Bn = B1b + (s+1)*1536;
            pbz = __ldg(Bn); pbr = __ldg(Bn + 512); pbh = __ldg(Bn + 1024);
            MMA_GATE(az,  cz, a0, a1);
            MMA_GATE(ar,  cr, a0, a1);
            MMA_GATE(arh, ch, a0, a1);
        }
        {   // x slab; chain prefetch -> GEMM2a (U2 slab 32)
            uint4 a0 = hAr[32*32 + lane];
            uint4 a1 = hAr[(L1_SLABS + 32)*32 + lane];
            uint4 cz = pbz, cr = pbr, ch = pbh;
            const uint4* Bn = B2b + 32*1536;
            pbz = __ldg(Bn); pbr = __ldg(Bn + 512); pbh = __ldg(Bn + 1024);
            MMA_GATE(az,  cz, a0, a1);
            MMA_GATE(ar,  cr, a0, a1);
            MMA_GATE(axh, ch, a0, a1);
        }

        // ---- layer 1 gate math (state in hF1, full fp32) ----
        #pragma unroll
        for (int tt = 0; tt < 2; tt++)
            #pragma unroll
            for (int cc = 0; cc < 2; cc++){
                int uc = u0 + tt*8 + 2*lc + cc;
                float bz  = b1s[uc]       + b1s[G3 + uc];
                float br  = b1s[256 + uc] + b1s[G3 + 256 + uc];
                float bxh = b1s[512 + uc];
                float brh = b1s[G3 + 512 + uc];
                #pragma unroll
                for (int m = 0; m < 2; m++)
                    #pragma unroll
                    for (int hi = 0; hi < 2; hi++){
                        int c = hi*2 + cc;
                        int row = 16*m + lr + 8*hi;
                        float z = sigf(az[m][tt][c] + bz);
                        float r = sigf(ar[m][tt][c] + br);
                        float hh = tanhf_(axh[m][tt][c] + bxh + r*(arh[m][tt][c] + brh));
                        float ho = hF1[row*HFS + uc];
                        float v  = z*ho + (1.f - z)*hh;
                        hF1[row*HFS + uc] = v;
                        hn[m][tt][c] = v;
                    }
            }
        // store h1_new into write buffer (no barrier needed: nobody reads it
        // until after B1)
        #pragma unroll
        for (int tt = 0; tt < 2; tt++)
            #pragma unroll
            for (int cc = 0; cc < 2; cc++){
                int kc = 2*lc + cc, lcc = kc & 3, q = kc >> 2;
                #pragma unroll
                for (int m = 0; m < 2; m++)
                    #pragma unroll
                    for (int hi = 0; hi < 2; hi++)
                        hWf[((m*L1_SLABS + warp*2 + tt)*32 + lr*4 + lcc)*4
                            + hi + 2*q] = f2tf(hn[m][tt][hi*2 + cc]);
            }

        // ================= GEMM2a: h2_old @ U2 (blob slabs 32..63) ========
        ZERO_ACC;
        #pragma unroll 2
        for (int s = 0; s < 32; s++){
            uint4 a0 = hA2u[s*32 + lane];
            uint4 a1 = hA2u[(32 + s)*32 + lane];
            uint4 cz = pbz, cr = pbr, ch = pbh;
            const uint4* Bn = (s < 31) ? (B2b + (33 + s)*1536) : B2b;  // chain -> W2 slab 0
            pbz = __ldg(Bn); pbr = __ldg(Bn + 512); pbh = __ldg(Bn + 1024);
            MMA_GATE(az,  cz, a0, a1);
            MMA_GATE(ar,  cr, a0, a1);
            MMA_GATE(arh, ch, a0, a1);
        }
        __syncthreads();                                   // B1: h1_new visible

        // ================= GEMM2b: h1_new @ W2 (blob slabs 0..31) =========
        #pragma unroll 2
        for (int s = 0; s < 32; s++){
            uint4 a0 = hAw[s*32 + lane];
            uint4 a1 = hAw[(L1_SLABS + s)*32 + lane];
            uint4 cz = pbz, cr = pbr, ch = pbh;
            const uint4* Bn = (s < 31) ? (B2b + (s+1)*1536) : B1b;     // chain -> next GEMM1
            pbz = __ldg(Bn); pbr = __ldg(Bn + 512); pbh = __ldg(Bn + 1024);
            MMA_GATE(az,  cz, a0, a1);
            MMA_GATE(ar,  cr, a0, a1);
            MMA_GATE(axh, ch, a0, a1);
        }

        // ---- layer 2 gate math + h2 store + pred partials ----
        float ps[4][5];
        #pragma unroll
        for (int ri = 0; ri < 4; ri++)
            #pragma unroll
            for (int o = 0; o < 5; o++) ps[ri][o] = 0.f;

        #pragma unroll
        for (int tt = 0; tt < 2; tt++)
            #pragma unroll
            for (int cc = 0; cc < 2; cc++){
                int uc = u0 + tt*8 + 2*lc + cc;
                float bz  = b2s[uc]       + b2s[G3 + uc];
                float br  = b2s[256 + uc] + b2s[G3 + 256 + uc];
                float bxh = b2s[512 + uc];
                float brh = b2s[G3 + 512 + uc];
                float wdv[5];
                #pragma unroll
                for (int o = 0; o < 5; o++) wdv[o] = wds[uc*5 + o];
                #pragma unroll
                for (int m = 0; m < 2; m++)
                    #pragma unroll
                    for (int hi = 0; hi < 2; hi++){
                        int c = hi*2 + cc;
                        int row = 16*m + lr + 8*hi;
                        float z = sigf(az[m][tt][c] + bz);
                        float r = sigf(ar[m][tt][c] + br);
                        float hh = tanhf_(axh[m][tt][c] + bxh + r*(arh[m][tt][c] + brh));
                        float ho = hF2[row*HFS + uc];
                        float v  = z*ho + (1.f - z)*hh;
                        hF2[row*HFS + uc] = v;
                        hn[m][tt][c] = v;
                        int ri = 2*m + hi;   // row = lr + 8*ri
                        #pragma unroll
                        for (int o = 0; o < 5; o++) ps[ri][o] += v * wdv[o];
                    }
            }
        // store h2_new to hA2 (WAR-safe: all hA2 reads happened before B1)
        #pragma unroll
        for (int tt = 0; tt < 2; tt++)
            #pragma unroll
            for (int cc = 0; cc < 2; cc++){
                int kc = 2*lc + cc, lcc = kc & 3, q = kc >> 2;
                #pragma unroll
                for (int m = 0; m < 2; m++)
                    #pragma unroll
                    for (int hi = 0; hi < 2; hi++)
                        sm[OFF_HA2 + ((m*32 + warp*2 + tt)*32 + lr*4 + lcc)*4
                           + hi + 2*q] = f2tf(hn[m][tt][hi*2 + cc]);
            }
        // reduce pred partials over the 4 lc lanes
        #pragma unroll
        for (int ri = 0; ri < 4; ri++)
            #pragma unroll
            for (int o = 0; o < 5; o++){
                ps[ri][o] += __shfl_xor_sync(0xffffffffu, ps[ri][o], 1);
                ps[ri][o] += __shfl_xor_sync(0xffffffffu, ps[ri][o], 2);
            }
        if (lc == 0){
            #pragma unroll
            for (int ri = 0; ri < 4; ri++)
                #pragma unroll
                for (int o = 0; o < 5; o++)
                    part[warp*160 + (lr + 8*ri)*5 + o] = ps[ri][o];
        }
        __syncthreads();                                   // B2: part + h2 visible

        // final pred reduce + output + stage decode-x (k=1..5) for t+1
        if (tid < 160){
            int row = tid / 5, o = tid % 5;
            float s = bds[o];
            #pragma unroll
            for (int w = 0; w < 16; w++) s += part[w*160 + tid];
            int grow = row0 + row;
            int tout = (t < WARM) ? t : t + 1;
            out[(size_t)grow*960 + tout*5 + o] = s;
            if (t == WARM - 1) out[(size_t)grow*960 + WARM*5 + o] = s;
            if (t + 1 >= WARM && t + 1 < TSTEPS){
                int k = o + 1;                 // pred feeds x[1..5]
                int m = row >> 4, r = row & 15, rl = r & 7, hi2 = r >> 3;
                int lcc = k & 3, q = k >> 2;
                hWf[((m*L1_SLABS + 32)*32 + rl*4 + lcc)*4 + hi2 + 2*q] = f2tf(s);
            }
        }
        // stage x[k=0] (Q) or full warmup x for t+1 (into write buffer)
        if (tid < NROWS && t + 1 < TSTEPS){
            int row = tid;
            int m = row >> 4, r = row & 15, rl = r & 7, hi2 = r >> 3;
            if (t + 1 < WARM){
                const float* ip = inputs + ((size_t)(row0 + row)*192 + (t + 1))*6;
                #pragma unroll
                for (int k = 0; k < 6; k++){
                    int lcc = k & 3, q = k >> 2;
                    hWf[((m*L1_SLABS + 32)*32 + rl*4 + lcc)*4 + hi2 + 2*q] = f2tf(ip[k]);
                }
            } else {
                float qv = qpre[row*127 + (t + 1 - WARM)];
                hWf[((m*L1_SLABS + 32)*32 + rl*4 + 0)*4 + hi2] = f2tf(qv);
            }
        }
        __syncthreads();                                   // B3: x_{t+1} visible
    }
}

// ---------------------------------------------------------------------------
extern "C" void kernel_launch(void* const* d_in, const int* in_sizes, int n_in,
                              void* d_out, int out_size) {
    (void)in_sizes; (void)n_in; (void)out_size;
    const float* inputs = (const float*)d_in[0];
    const float* W1 = (const float*)d_in[1];
    const float* U1 = (const float*)d_in[2];
    const float* b1 = (const float*)d_in[3];
    const float* W2 = (const float*)d_in[4];
    const float* U2 = (const float*)d_in[5];
    const float* b2 = (const float*)d_in[6];
    const float* Wd = (const float*)d_in[7];
    const float* bd = (const float*)d_in[8];
    float* out = (float*)d_out;

    cudaFuncSetAttribute(gru_kernel, cudaFuncAttributeMaxDynamicSharedMemorySize,
                         SMEM_BYTES);
    prep_kernel<<<(TOT_F4 + 255)/256, 256>>>(W1, U1, W2, U2);
    gru_kernel<<<NCTA, NTHREADS, SMEM_BYTES>>>(inputs, b1, b2, Wd, bd, out);
}